// round 11
// baseline (speedup 1.0000x reference)
#include <cuda_runtime.h>
#include <cstdint>

typedef unsigned long long ull;

// Problem constants
#define BT   512          // batches
#define TT   4096         // timesteps
#define CH   64           // steps per chunk
#define NCH  (TT / CH)    // 64 chunks
#define NBLK 16           // blocks (each fully independent)
#define BPB  32           // batches per block
#define NTHR 128          // 4 warps

#define DT_F     0.001f
#define C_F      1.6970562748477140f      // sqrt(4*ETA*KAPPA) = sqrt(2.88)
#define NDTC2    (-0.00288f)              // -DT * C^2
#define KX_F     (1.0f - 0.00015f)        // 1 - 0.5*GAMMA*DT
#define KCOV_F   (1.0f - 0.0003f)         // 1 - GAMMA*DT
#define DTD_F    (0.00165f)               // DT * (GAMMA*(NBAR+0.5)+KAPPA)
#define CDT_F    (C_F * DT_F)

// smem layout (bytes):
//   dyS : float2[3][32][66]   = 50688  @ 0       (dy ring; row 528B, cp.async-aligned)
//   cfS : float4[2][64]       =  2048  @ 50688   (a00, a10, C*vx, C*cxp per step)
//   fS  : float2[2][64][32]   = 32768  @ 52736   (per-(step,batch) forcing)
//   oS  : float2[2][32][33]   = 16896  @ 85504   (raw pre-update x0, packed pairs)
//   rawS: float2[3][64]       =  1536  @ 102400  (riccati raw (vx,cxp) ring)
//   finS: float4              =    16  @ 103936
#define DYS_BUF_F2  2112
#define FS_BUF_F2   2048
#define OS_BUF_F2   1056
#define SMEM_CF_OFF 50688
#define SMEM_FS_OFF 52736
#define SMEM_OS_OFF 85504
#define SMEM_RAW    102400
#define SMEM_FIN    103936
#define SMEM_TOTAL  103952

static __device__ __forceinline__ uint32_t smem_u32(const void* p) {
    uint32_t a;
    asm("{ .reg .u64 t; cvta.to.shared.u64 t, %1; cvt.u32.u64 %0, t; }" : "=r"(a) : "l"(p));
    return a;
}
static __device__ __forceinline__ void cp_async16(uint32_t dst, const void* src) {
    asm volatile("cp.async.cg.shared.global [%0], [%1], 16;" :: "r"(dst), "l"(src));
}
#define CP_COMMIT() asm volatile("cp.async.commit_group;" ::: "memory")
#define CP_WAIT1()  asm volatile("cp.async.wait_group 1;" ::: "memory")
#define CP_WAIT0()  asm volatile("cp.async.wait_group 0;" ::: "memory")

#define F32X2_FMA(out, a, b, c) \
    asm("fma.rn.f32x2 %0, %1, %2, %3;" : "=l"(out) : "l"(a), "l"(b), "l"(c))
#define PACK2(out, lo, hi) \
    asm("mov.b64 %0, {%1, %2};" : "=l"(out) : "f"(lo), "f"(hi))
#define UNPACK2(lo, hi, in) \
    asm("mov.b64 {%0, %1}, %2;" : "=f"(lo), "=f"(hi) : "l"(in))

__global__ void __launch_bounds__(NTHR, 1)
grnn_kernel(const float* __restrict__ dy,
            const float* __restrict__ state0,
            const float* __restrict__ omega_p,
            float*       __restrict__ out)
{
    extern __shared__ char sm[];
    float2* dyS  = reinterpret_cast<float2*>(sm);                 // [3][32][66]
    float4* cfS  = reinterpret_cast<float4*>(sm + SMEM_CF_OFF);   // [2][64]
    float2* fS   = reinterpret_cast<float2*>(sm + SMEM_FS_OFF);   // [2][64][32]
    float2* oS   = reinterpret_cast<float2*>(sm + SMEM_OS_OFF);   // [2][32][33]
    float2* rawS = reinterpret_cast<float2*>(sm + SMEM_RAW);      // [3][64]
    float4* finS = reinterpret_cast<float4*>(sm + SMEM_FIN);

    const int tid  = threadIdx.x;
    const int lane = tid & 31;
    const int wid  = tid >> 5;
    const int blk  = blockIdx.x;
    const int b    = blk * BPB + lane;

    const float w     = omega_p[0];
    const float wdt   = w * DT_F;
    const float nwdt  = -wdt;
    const float w2dt  = 2.0f * wdt;
    const float nw2dt = -w2dt;
    ull W2W; PACK2(W2W, w2dt, wdt);     // packed (w2dt, wdt)

    const float2* dyb = reinterpret_cast<const float2*>(dy) + (size_t)b * TT;
    float2*       dyh = reinterpret_cast<float2*>(out + 6 * BT);

    // Per-warp persistent state
    float x0 = 0.f, x1 = 0.f;           // w0
    ull   vc = 0;  float vp = 0.f;      // w1 lane0: packed (vx,cxp), scalar vp

    // w1: Riccati raw chunk p -> rawS slot p%3 (pre-update (vx,cxp) pairs)
    auto riccati_raw = [&](int p) {
        ull* rg = reinterpret_cast<ull*>(rawS + (p % 3) * CH);
#pragma unroll 16
        for (int s = 0; s < CH; ++s) {
            rg[s] = vc;
            float vx, cxp; UNPACK2(vx, cxp, vc);
            const float m = fmaf(NDTC2, vx, KCOV_F);
            const float t = nwdt * vx;
            ull cv;  PACK2(cv,  cxp,   vp);
            ull dt2; PACK2(dt2, DTD_F, t);
            ull gh;  F32X2_FMA(gh, W2W, cv, dt2);     // (g, h)
            ull mm;  PACK2(mm, m, m);
            ull nvc; F32X2_FMA(nvc, mm, vc, gh);      // (nvx, ncxp)
            const float u = fmaf(NDTC2, cxp, nw2dt);
            const float q = fmaf(u, cxp, DTD_F);
            vp = fmaf(KCOV_F, vp, q);
            vc = nvc;
        }
    };

    // w2: derive batch-independent coefs for chunk p (2 steps per lane)
    auto derive = [&](int p) {
        const float4 r = *reinterpret_cast<const float4*>(&rawS[(p % 3) * CH + 2 * lane]);
        float4* cg = cfS + (p & 1) * CH;
        cg[2 * lane]     = make_float4(fmaf(NDTC2, r.x, KX_F), fmaf(NDTC2, r.y, nwdt),
                                       C_F * r.x, C_F * r.y);
        cg[2 * lane + 1] = make_float4(fmaf(NDTC2, r.z, KX_F), fmaf(NDTC2, r.w, nwdt),
                                       C_F * r.z, C_F * r.w);
    };

    // w2: per-(step,batch) forcing for chunk p (reads OWN lane's staged dy rows)
    auto forcing = [&](int p) {
        const float4* cf = cfS + (p & 1) * CH;
        const float4* dr = reinterpret_cast<const float4*>(
                               &dyS[(p % 3) * DYS_BUF_F2 + lane * 66]);
        float2* fp = fS + (p & 1) * FS_BUF_F2 + lane;
#pragma unroll 8
        for (int s = 0; s < CH; s += 2) {
            const float4 d2 = dr[s >> 1];           // dy: steps s (x), s+1 (z)
            const float4 k0 = cf[s];
            const float4 k1 = cf[s + 1];
            fp[s * 32]       = make_float2(k0.z * d2.x, k0.w * d2.x);
            fp[(s + 1) * 32] = make_float2(k1.z * d2.z, k1.w * d2.z);
        }
    };

    // w2: stage dy chunk c into ring slot c%3
    auto stage = [&](int c) {
        const float2*  src = dyb + c * CH;
        const uint32_t dst = smem_u32(&dyS[(c % 3) * DYS_BUF_F2 + lane * 66]);
#pragma unroll
        for (int k = 0; k < CH / 2; ++k) cp_async16(dst + k * 16, src + 2 * k);
        CP_COMMIT();
    };

    // w3: flush chunk fc (applies CDT_F scaling; lane = step-pair)
    auto flush = [&](int fc) {
        const float2* ou = oS + (fc & 1) * OS_BUF_F2 + lane * 33;
        float2* fb = dyh + (size_t)(blk * BPB) * TT + fc * CH + 2 * lane;
#pragma unroll
        for (int g = 0; g < 4; ++g) {
            float2 v[8];
#pragma unroll
            for (int i = 0; i < 8; ++i) v[i] = ou[8 * g + i];
#pragma unroll
            for (int i = 0; i < 8; ++i)
                *reinterpret_cast<float4*>(fb + (size_t)(8 * g + i) * TT) =
                    make_float4(CDT_F * v[i].x, 0.f, CDT_F * v[i].y, 0.f);
        }
    };

    // ---------------- prologue ----------------
    if (wid == 0) {
        x0 = state0[(size_t)b * 6 + 0];
        x1 = state0[(size_t)b * 6 + 1];
    } else if (wid == 1 && lane == 0) {
        float vx  = state0[2];
        float cxp = state0[4];
        vp = state0[3];
        PACK2(vc, vx, cxp);
        riccati_raw(0);
        riccati_raw(1);
    } else if (wid == 2) {
        stage(0);
        stage(1);
    }
    __syncthreads();
    if (wid == 2) {
        CP_WAIT1();          // dy chunk 0 resident (own lanes)
        derive(0);
        __syncwarp();
        forcing(0);
    }
    __syncthreads();

    // ---------------- main loop ----------------
    for (int c = 0; c < NCH; ++c) {
        if (wid == 0) {
            // x-chain: minimal issue — LDS.128 + LDS.64 + 4 FMA per step
            const float4* cf = cfS + (c & 1) * CH;
            const float2* fp = fS + (c & 1) * FS_BUF_F2 + lane;
            float2*       op = oS + (c & 1) * OS_BUF_F2 + lane;
#pragma unroll
            for (int s = 0; s < CH; s += 2) {
                const float4 k0 = cf[s];
                const float4 k1 = cf[s + 1];
                const float2 f0 = fp[s * 32];
                const float2 f1 = fp[(s + 1) * 32];
                const float  xa = x0;                       // pre-update x0, step s
                const float  y0 = fmaf(k0.x, x0, fmaf(wdt,  x1, f0.x));
                const float  y1 = fmaf(k0.y, x0, fmaf(KX_F, x1, f0.y));
                // y0 = pre-update x0 for step s+1
                x0 = fmaf(k1.x, y0, fmaf(wdt,  y1, f1.x));
                x1 = fmaf(k1.y, y0, fmaf(KX_F, y1, f1.y));
                op[(s >> 1) * 33] = make_float2(xa, y0);    // raw; flush scales
            }
        } else if (wid == 1) {
            if (lane == 0 && c + 2 < NCH) {
                riccati_raw(c + 2);
                if (c + 2 == NCH - 1) {
                    float vx, cxp; UNPACK2(vx, cxp, vc);
                    *finS = make_float4(vx, vp, cxp, state0[5] + DT_F * (float)TT);
                }
            }
        } else if (wid == 2) {
            if (c + 2 < NCH)      { stage(c + 2); CP_WAIT1(); }   // chunk c+1 resident
            else if (c + 2 == NCH) CP_WAIT0();                    // drain last chunk
            if (c + 1 < NCH) {
                derive(c + 1);
                __syncwarp();
                forcing(c + 1);
            }
        } else {  // wid == 3
            if (c >= 1) flush(c - 1);
        }
        __syncthreads();
    }

    // ---------------- epilogue ----------------
    if (wid == 3) {
        flush(NCH - 1);
    } else if (wid == 0) {
        const float4 f = *finS;
        float* fs = out + (size_t)b * 6;
        fs[0] = x0;
        fs[1] = x1;
        fs[2] = f.x;   // vx  = ncov[0,0]
        fs[3] = f.y;   // vp  = ncov[1,1]
        fs[4] = f.z;   // cxp = ncov[1,0]
        fs[5] = f.w;   // t
    }
}

extern "C" void kernel_launch(void* const* d_in, const int* in_sizes, int n_in,
                              void* d_out, int out_size)
{
    const float* dy      = (const float*)d_in[0];
    const float* state0  = (const float*)d_in[1];
    const float* omega_p = (const float*)d_in[2];
    float*       out     = (float*)d_out;
    (void)in_sizes; (void)n_in; (void)out_size;

    cudaFuncSetAttribute(grnn_kernel,
                         cudaFuncAttributeMaxDynamicSharedMemorySize, SMEM_TOTAL);
    grnn_kernel<<<NBLK, NTHR, SMEM_TOTAL>>>(dy, state0, omega_p, out);
}

// round 12
// speedup vs baseline: 1.2912x; 1.2912x over previous
#include <cuda_runtime.h>
#include <cstdint>

typedef unsigned long long ull;

// Problem constants
#define BT   512          // batches
#define TT   4096         // timesteps
#define CH   64           // steps per chunk
#define NP   32           // step-pairs per chunk
#define NCH  (TT / CH)    // 64 chunks
#define NBLK 16           // blocks (each fully independent)
#define BPB  32           // batches per block
#define NTHR 128          // 4 warps

#define DT_F     0.001f
#define C_F      1.6970562748477140f      // sqrt(4*ETA*KAPPA) = sqrt(2.88)
#define NDTC2    (-0.00288f)              // -DT * C^2
#define KX_F     (1.0f - 0.00015f)        // 1 - 0.5*GAMMA*DT
#define KCOV_F   (1.0f - 0.0003f)         // 1 - GAMMA*DT
#define DTD_F    (0.00165f)               // DT * (GAMMA*(NBAR+0.5)+KAPPA)
#define CDT_F    (C_F * DT_F)

// smem layout (bytes):
//   dyS : float2[4][32][66] = 67584 @ 0      (dy ring of 4; row 528B, cp.async-aligned)
//   bS  : float4[2][32]     =  1024 @ 67584  (pair map B = A_o A_e)
//   ghS : float4[2][32]     =  1024 @ 68608  (pair forcing vectors g, h)
//   rcS : float2[2][32]     =   512 @ 69632  (a00_e, c*vx_e for odd-step reconstruction)
//   oS  : float2[2][32][33] = 16896 @ 70144  (pre-update (x0,x1) at even steps)
//   rawS: float2[3][64]     =  1536 @ 87040  (riccati raw (vx,cxp) ring)
//   finS: float4            =    16 @ 88576
#define DYS_BUF_F2  2112
#define OS_BUF_F2   1056
#define SMEM_B_OFF  67584
#define SMEM_GH_OFF 68608
#define SMEM_RC_OFF 69632
#define SMEM_OS_OFF 70144
#define SMEM_RAW    87040
#define SMEM_FIN    88576
#define SMEM_TOTAL  88592

static __device__ __forceinline__ uint32_t smem_u32(const void* p) {
    uint32_t a;
    asm("{ .reg .u64 t; cvta.to.shared.u64 t, %1; cvt.u32.u64 %0, t; }" : "=r"(a) : "l"(p));
    return a;
}
static __device__ __forceinline__ void cp_async16(uint32_t dst, const void* src) {
    asm volatile("cp.async.cg.shared.global [%0], [%1], 16;" :: "r"(dst), "l"(src));
}
#define CP_COMMIT() asm volatile("cp.async.commit_group;" ::: "memory")
#define CP_WAIT1()  asm volatile("cp.async.wait_group 1;" ::: "memory")
#define CP_WAIT0()  asm volatile("cp.async.wait_group 0;" ::: "memory")

#define F32X2_FMA(out, a, b, c) \
    asm("fma.rn.f32x2 %0, %1, %2, %3;" : "=l"(out) : "l"(a), "l"(b), "l"(c))
#define PACK2(out, lo, hi) \
    asm("mov.b64 %0, {%1, %2};" : "=l"(out) : "f"(lo), "f"(hi))
#define UNPACK2(lo, hi, in) \
    asm("mov.b64 {%0, %1}, %2;" : "=f"(lo), "=f"(hi) : "l"(in))

__global__ void __launch_bounds__(NTHR, 1)
grnn_kernel(const float* __restrict__ dy,
            const float* __restrict__ state0,
            const float* __restrict__ omega_p,
            float*       __restrict__ out)
{
    extern __shared__ char sm[];
    float2* dyS  = reinterpret_cast<float2*>(sm);                 // [4][32][66]
    float4* bS   = reinterpret_cast<float4*>(sm + SMEM_B_OFF);    // [2][32]
    float4* ghS  = reinterpret_cast<float4*>(sm + SMEM_GH_OFF);   // [2][32]
    float2* rcS  = reinterpret_cast<float2*>(sm + SMEM_RC_OFF);   // [2][32]
    float2* oS   = reinterpret_cast<float2*>(sm + SMEM_OS_OFF);   // [2][32*33]
    float2* rawS = reinterpret_cast<float2*>(sm + SMEM_RAW);      // [3][64]
    float4* finS = reinterpret_cast<float4*>(sm + SMEM_FIN);

    const int tid  = threadIdx.x;
    const int lane = tid & 31;
    const int wid  = tid >> 5;
    const int blk  = blockIdx.x;
    const int b    = blk * BPB + lane;

    const float w     = omega_p[0];
    const float wdt   = w * DT_F;
    const float nwdt  = -wdt;
    const float w2dt  = 2.0f * wdt;
    const float nw2dt = -w2dt;
    ull W2W; PACK2(W2W, w2dt, wdt);     // packed (w2dt, wdt)

    const float2* dyb = reinterpret_cast<const float2*>(dy) + (size_t)b * TT;
    float2*       dyh = reinterpret_cast<float2*>(out + 6 * BT);

    // Per-warp persistent state
    float x0 = 0.f, x1 = 0.f;           // w0
    ull   vc = 0;  float vp = 0.f;      // w1 lane0: packed (vx,cxp), scalar vp

    // w1: Riccati raw chunk p -> rawS slot p%3 (pre-update (vx,cxp) pairs)
    auto riccati_raw = [&](int p) {
        ull* rg = reinterpret_cast<ull*>(rawS + (p % 3) * CH);
#pragma unroll 16
        for (int s = 0; s < CH; ++s) {
            rg[s] = vc;
            float vx, cxp; UNPACK2(vx, cxp, vc);
            const float m = fmaf(NDTC2, vx, KCOV_F);
            const float t = nwdt * vx;
            ull cv;  PACK2(cv,  cxp,   vp);
            ull dt2; PACK2(dt2, DTD_F, t);
            ull gh;  F32X2_FMA(gh, W2W, cv, dt2);     // (g, h)
            ull mm;  PACK2(mm, m, m);
            ull nvc; F32X2_FMA(nvc, mm, vc, gh);      // (nvx, ncxp)
            const float u = fmaf(NDTC2, cxp, nw2dt);
            const float q = fmaf(u, cxp, DTD_F);
            vp = fmaf(KCOV_F, vp, q);
            vc = nvc;
        }
    };

    // w2: derive pair-composed maps for chunk q (lane = pair index)
    // x_{s+2} = B x_s + d_e*g + d_o*h;  B, g, h batch-independent.
    auto derive = [&](int q) {
        const float4 r = *reinterpret_cast<const float4*>(&rawS[(q % 3) * CH + 2 * lane]);
        // r = (vx_e, cxp_e, vx_o, cxp_o) pre-update
        const float a00e = fmaf(NDTC2, r.x, KX_F);
        const float a10e = fmaf(NDTC2, r.y, nwdt);
        const float a00o = fmaf(NDTC2, r.z, KX_F);
        const float a10o = fmaf(NDTC2, r.w, nwdt);
        const float cvxe = C_F * r.x, ccxpe = C_F * r.y;
        const float cvxo = C_F * r.z, ccxpo = C_F * r.w;
        const int ob = (q & 1) * NP + lane;
        bS[ob]  = make_float4(fmaf(a00o, a00e, wdt * a10e),    // B00
                              fmaf(a00o, wdt,  wdt * KX_F),    // B01
                              fmaf(a10o, a00e, KX_F * a10e),   // B10
                              fmaf(a10o, wdt,  KX_F * KX_F));  // B11
        ghS[ob] = make_float4(fmaf(a00o, cvxe, wdt * ccxpe),   // g0
                              fmaf(a10o, cvxe, KX_F * ccxpe),  // g1
                              cvxo, ccxpo);                    // h0, h1
        rcS[ob] = make_float2(a00e, cvxe);                     // for odd-step recon
    };

    // w2: stage dy chunk c into ring slot c%4
    auto stage = [&](int c) {
        const float2*  src = dyb + c * CH;
        const uint32_t dst = smem_u32(&dyS[(c % 4) * DYS_BUF_F2 + lane * 66]);
#pragma unroll
        for (int k = 0; k < CH / 2; ++k) cp_async16(dst + k * 16, src + 2 * k);
        CP_COMMIT();
    };

    // w3: flush chunk fc — reconstruct odd-step x0, scale, coalesced STG.128
    auto flush = [&](int fc) {
        const int     ob   = fc & 1;
        const float2  rc   = rcS[ob * NP + lane];              // (a00_e, c*vx_e)
        const float2* ou   = oS + ob * OS_BUF_F2 + lane * 33;  // row = this pair
        const float2* dRow = dyS + (fc % 4) * DYS_BUF_F2;      // + bb*66 + 2*lane
        float2* fb = dyh + (size_t)(blk * BPB) * TT + fc * CH + 2 * lane;
#pragma unroll 8
        for (int bb = 0; bb < BPB; ++bb) {
            const float2 xp = ou[bb];                          // (x0e, x1e) pre-update
            const float  d  = dRow[bb * 66 + 2 * lane].x;      // dy even step
            const float x0o = fmaf(rc.x, xp.x, fmaf(wdt, xp.y, rc.y * d));
            *reinterpret_cast<float4*>(fb + (size_t)bb * TT) =
                make_float4(CDT_F * xp.x, 0.f, CDT_F * x0o, 0.f);
        }
    };

    // ---------------- prologue ----------------
    if (wid == 0) {
        x0 = state0[(size_t)b * 6 + 0];
        x1 = state0[(size_t)b * 6 + 1];
    } else if (wid == 1 && lane == 0) {
        float vx  = state0[2];
        float cxp = state0[4];
        vp = state0[3];
        PACK2(vc, vx, cxp);
        riccati_raw(0);
        riccati_raw(1);
    } else if (wid == 2) {
        stage(0);
        stage(1);
    }
    __syncthreads();
    if (wid == 2) {
        derive(0);           // pair maps for chunk 0 (raw0 ready)
        CP_WAIT1();          // dy chunk 0 resident
    }
    __syncthreads();

    // ---------------- main loop ----------------
    for (int c = 0; c < NCH; ++c) {
        if (wid == 0) {
            // x-chain: 32 composed pairs (3 LDS.128 + 8 FMA + STS.64 each)
            const float4* bP  = bS  + (c & 1) * NP;
            const float4* gP  = ghS + (c & 1) * NP;
            const float4* dr4 = reinterpret_cast<const float4*>(
                                    &dyS[(c % 4) * DYS_BUF_F2 + lane * 66]);
            float2* op = oS + (c & 1) * OS_BUF_F2 + lane;
#pragma unroll
            for (int p = 0; p < NP; ++p) {
                const float4 B  = bP[p];                // broadcast
                const float4 G  = gP[p];                // broadcast
                const float4 d2 = dr4[p];               // dy: even (.x), odd (.z)
                op[p * 33] = make_float2(x0, x1);       // pre-update at even step
                const float F0  = fmaf(d2.x, G.x, d2.z * G.z);
                const float F1  = fmaf(d2.x, G.y, d2.z * G.w);
                const float nx0 = fmaf(B.x, x0, fmaf(B.y, x1, F0));
                const float nx1 = fmaf(B.z, x0, fmaf(B.w, x1, F1));
                x0 = nx0; x1 = nx1;
            }
        } else if (wid == 1) {
            if (lane == 0 && c + 2 < NCH) {
                riccati_raw(c + 2);
                if (c + 2 == NCH - 1) {
                    float vx, cxp; UNPACK2(vx, cxp, vc);
                    *finS = make_float4(vx, vp, cxp, state0[5] + DT_F * (float)TT);
                }
            }
        } else if (wid == 2) {
            if (c + 2 < NCH)      { stage(c + 2); CP_WAIT1(); }   // chunk c+1 resident
            else if (c + 2 == NCH) CP_WAIT0();                    // drain last chunk
            if (c + 1 < NCH) derive(c + 1);
        } else {  // wid == 3
            if (c >= 1) flush(c - 1);
        }
        __syncthreads();
    }

    // ---------------- epilogue ----------------
    if (wid == 3) {
        flush(NCH - 1);
    } else if (wid == 0) {
        const float4 f = *finS;
        float* fs = out + (size_t)b * 6;
        fs[0] = x0;
        fs[1] = x1;
        fs[2] = f.x;   // vx  = ncov[0,0]
        fs[3] = f.y;   // vp  = ncov[1,1]
        fs[4] = f.z;   // cxp = ncov[1,0]
        fs[5] = f.w;   // t
    }
}

extern "C" void kernel_launch(void* const* d_in, const int* in_sizes, int n_in,
                              void* d_out, int out_size)
{
    const float* dy      = (const float*)d_in[0];
    const float* state0  = (const float*)d_in[1];
    const float* omega_p = (const float*)d_in[2];
    float*       out     = (float*)d_out;
    (void)in_sizes; (void)n_in; (void)out_size;

    cudaFuncSetAttribute(grnn_kernel,
                         cudaFuncAttributeMaxDynamicSharedMemorySize, SMEM_TOTAL);
    grnn_kernel<<<NBLK, NTHR, SMEM_TOTAL>>>(dy, state0, omega_p, out);
}